// round 11
// baseline (speedup 1.0000x reference)
#include <cuda_runtime.h>
#include <cuda_bf16.h>
#include <cstdint>

#define NN 50000
#define EE 800000
#define ET (EE + NN)
#define HID 128
#define HEADS 8
#define NOUT 19
#define HF 152
#define SLOPE 0.2f
#define SEPS 1e-16f
#define NB 49  // ceil(NN/1024)

// permuted feature index f' = o*8+h  ->  original index h*19+o
#define ORIG(f) ((((f) & 7) * 19) + ((f) >> 3))

// ================= scratch =================
__device__ float g_h[NN * HID];
__device__ float g_xp[NN * HF];      // PERMUTED feature order (fp32)
__device__ float g_als[NN * HEADS];
__device__ float g_ald[NN * HEADS];
__device__ float g_alpha[(size_t)ET * HEADS];  // logits, then softmax weights
__device__ int g_off[NN + 1];
__device__ int g_cur[NN];
__device__ int g_part[64];
__device__ int g_ssrc[ET];
// pre-split bf16 hi/lo packed pairs
__device__ __align__(16) uint32_t g_hhi[NN * 64];
__device__ __align__(16) uint32_t g_hlo[NN * 64];
__device__ __align__(16) uint32_t g_uhi[NN * 80];
__device__ __align__(16) uint32_t g_ulo[NN * 80];
__device__ __align__(16) uint32_t g_w1hi[3 * 152 * 64];
__device__ __align__(16) uint32_t g_w1lo[3 * 152 * 64];
__device__ __align__(16) uint32_t g_w2hi[3 * 128 * 80];
__device__ __align__(16) uint32_t g_w2lo[3 * 128 * 80];

__device__ __forceinline__ void split_bf16(float a, float b, uint32_t& hi, uint32_t& lo) {
    __nv_bfloat162 h2 = __floats2bfloat162_rn(a, b);
    float la = a - __bfloat162float(h2.x);
    float lb = b - __bfloat162float(h2.y);
    __nv_bfloat162 l2 = __floats2bfloat162_rn(la, lb);
    hi = *(uint32_t*)&h2;
    lo = *(uint32_t*)&l2;
}

__device__ __forceinline__ void mma_bf16(float* c, uint32_t a0, uint32_t a1, uint32_t a2,
                                         uint32_t a3, uint32_t b0, uint32_t b1) {
    asm volatile(
        "mma.sync.aligned.m16n8k16.row.col.f32.bf16.bf16.f32 "
        "{%0,%1,%2,%3}, {%4,%5,%6,%7}, {%8,%9}, {%0,%1,%2,%3};\n"
        : "+f"(c[0]), "+f"(c[1]), "+f"(c[2]), "+f"(c[3])
        : "r"(a0), "r"(a1), "r"(a2), "r"(a3), "r"(b0), "r"(b1));
}

#define LDMX4(r0, r1, r2, r3, a) \
    asm volatile("ldmatrix.sync.aligned.m8n8.x4.shared.b16 {%0,%1,%2,%3}, [%4];" \
        : "=r"(r0), "=r"(r1), "=r"(r2), "=r"(r3) : "r"(a))

__device__ __forceinline__ uint32_t smaddr(const void* p) {
    return (uint32_t)__cvta_generic_to_shared(p);
}
#define CP16(dst, src) \
    asm volatile("cp.async.cg.shared.global [%0], [%1], 16;" :: "r"(dst), "l"(src))
#define CPCOMMIT() asm volatile("cp.async.commit_group;" ::: "memory")
#define CPWAIT1() asm volatile("cp.async.wait_group 1;" ::: "memory")
#define CPWAIT0() asm volatile("cp.async.wait_group 0;" ::: "memory")

template <int KC, int NTP, int ASTR>
__device__ __forceinline__ void mma_block(uint32_t Ab, uint32_t Bb, float (*c)[4]) {
#pragma unroll
    for (int kc = 0; kc < KC; kc++) {
        uint32_t a0, a1, a2, a3;
        LDMX4(a0, a1, a2, a3, Ab + kc * 32);
#pragma unroll
        for (int ntp = 0; ntp < NTP; ntp++) {
            uint32_t b0, b1, b2, b3;
            LDMX4(b0, b1, b2, b3, Bb + ntp * 16 * ASTR + kc * 32);
            mma_bf16(c[2 * ntp], a0, a1, a2, a3, b0, b1);
            mma_bf16(c[2 * ntp + 1], a0, a1, a2, a3, b2, b3);
        }
    }
}

// ================= setup kernels =================
__global__ void embed_k(const int* __restrict__ z, const float* __restrict__ emb) {
    int idx = blockIdx.x * blockDim.x + threadIdx.x;
    int n = idx >> 5, q = idx & 31;
    if (n >= NN) return;
    int zi = z[n];
    float4 v = ((const float4*)(emb + zi * HID))[q];
    ((float4*)(g_h + n * HID))[q] = v;
    uint32_t h0, l0, h1, l1;
    split_bf16(v.x, v.y, h0, l0);
    split_bf16(v.z, v.w, h1, l1);
    g_hhi[n * 64 + 2 * q] = h0;
    g_hlo[n * 64 + 2 * q] = l0;
    g_hhi[n * 64 + 2 * q + 1] = h1;
    g_hlo[n * 64 + 2 * q + 1] = l1;
    if (q == 0) g_cur[n] = 1;  // self loop
}

__global__ void hist_k(const int* __restrict__ col) {
    int e = blockIdx.x * blockDim.x + threadIdx.x;
    if (e < EE) atomicAdd(&g_cur[col[e]], 1);
}

__global__ void wsplit_k(const float* __restrict__ gat_W, const float* __restrict__ ff_W) {
    int idx = blockIdx.x * blockDim.x + threadIdx.x;
    const int N1 = 3 * 152 * 64;
    if (idx < N1) {
        int b = idx / (152 * 64), rem = idx % (152 * 64);
        int n = rem >> 6, kp = rem & 63;
        const float* W = gat_W + b * HID * HF;
        int no = ORIG(n);
        float w0 = W[(2 * kp) * HF + no];
        float w1 = W[(2 * kp + 1) * HF + no];
        uint32_t hi, lo;
        split_bf16(w0, w1, hi, lo);
        g_w1hi[idx] = hi;
        g_w1lo[idx] = lo;
    } else if (idx < N1 + 3 * 128 * 80) {
        int j = idx - N1;
        int b = j / (128 * 80), rem = j % (128 * 80);
        int n = rem / 80, kp = rem % 80;
        uint32_t hi = 0, lo = 0;
        if (kp < 76) {
            const float* W = ff_W + b * HF * HID;
            float w0 = W[ORIG(2 * kp) * HID + n];
            float w1 = W[ORIG(2 * kp + 1) * HID + n];
            split_bf16(w0, w1, hi, lo);
        }
        g_w2hi[j] = hi;
        g_w2lo[j] = lo;
    }
}

__global__ void scan1_k() {
    __shared__ int wsum[32];
    int t = threadIdx.x, lane = t & 31, wid = t >> 5;
    int i = blockIdx.x * 1024 + t;
    int v = (i < NN) ? g_cur[i] : 0;
    int x = v;
#pragma unroll
    for (int d = 1; d < 32; d <<= 1) {
        int y = __shfl_up_sync(0xffffffffu, x, d);
        if (lane >= d) x += y;
    }
    if (lane == 31) wsum[wid] = x;
    __syncthreads();
    if (wid == 0) {
        int y = wsum[lane];
#pragma unroll
        for (int d = 1; d < 32; d <<= 1) {
            int z2 = __shfl_up_sync(0xffffffffu, y, d);
            if (lane >= d) y += z2;
        }
        wsum[lane] = y;
    }
    __syncthreads();
    int excl = (wid > 0 ? wsum[wid - 1] : 0) + x - v;
    if (i < NN) g_off[i] = excl;
    if (t == 1023) g_part[blockIdx.x] = wsum[31];
}

__global__ void scan23_k() {
    __shared__ int sp[64];
    int t = threadIdx.x;
    if (t < 32) {
        int v0 = (t < NB) ? g_part[t] : 0;
        int v1 = (t + 32 < NB) ? g_part[t + 32] : 0;
        int s0 = v0;
#pragma unroll
        for (int d = 1; d < 32; d <<= 1) {
            int y = __shfl_up_sync(0xffffffffu, s0, d);
            if (t >= d) s0 += y;
        }
        int tot0 = __shfl_sync(0xffffffffu, s0, 31);
        int s1 = v1;
#pragma unroll
        for (int d = 1; d < 32; d <<= 1) {
            int y = __shfl_up_sync(0xffffffffu, s1, d);
            if (t >= d) s1 += y;
        }
        sp[t] = s0 - v0;
        sp[t + 32] = tot0 + s1 - v1;
    }
    __syncthreads();
    int i = blockIdx.x * blockDim.x + t;
    if (i < NN) {
        int v = g_off[i] + sp[i >> 10];
        g_off[i] = v;
        g_cur[i] = v;
    }
    if (i == 0) g_off[NN] = ET;
}

__global__ void scatter_k(const int* __restrict__ row, const int* __restrict__ col) {
    int i = blockIdx.x * blockDim.x + threadIdx.x;
    if (i >= ET) return;
    int s, d;
    if (i < EE) { s = row[i]; d = col[i]; }
    else        { s = d = i - EE; }
    int p = atomicAdd(&g_cur[d], 1);
    g_ssrc[p] = s;
}

// ============ GEMM1: xp[N,152](perm) = h @ W1(perm); M128 x N-half ========
#define G1_ASTR 272
#define G1_AHI 0
#define G1_ALO 34816
#define G1_BHI 69632
#define G1_BLO 91392
#define G1_SMEM 113152

__global__ __launch_bounds__(256, 2) void gemm1_k(int blk) {
    extern __shared__ char sm[];
    uint32_t sb = smaddr(sm);
    int t = threadIdx.x, lane = t & 31, wid = t >> 5;
    int row0 = blockIdx.x * 128;
    int nh = blockIdx.y;
    int nthis = nh ? 9 : 10;
    int nColBase = nh * 80;
    int bRows = nthis * 8;
    const uint32_t* wh = g_w1hi + blk * 152 * 64;
    const uint32_t* wl = g_w1lo + blk * 152 * 64;

    for (int i = t; i < 128 * 16; i += 256) {
        int r = i >> 4, ch = i & 15;
        int gr = row0 + r;
        if (gr < NN) CP16(sb + G1_AHI + r * G1_ASTR + ch * 16, g_hhi + (size_t)gr * 64 + ch * 4);
    }
    for (int i = t; i < bRows * 16; i += 256) {
        int r = i >> 4, ch = i & 15;
        CP16(sb + G1_BHI + r * G1_ASTR + ch * 16, wh + (nColBase + r) * 64 + ch * 4);
    }
    CPCOMMIT();
    for (int i = t; i < 128 * 16; i += 256) {
        int r = i >> 4, ch = i & 15;
        int gr = row0 + r;
        if (gr < NN) CP16(sb + G1_ALO + r * G1_ASTR + ch * 16, g_hlo + (size_t)gr * 64 + ch * 4);
    }
    for (int i = t; i < bRows * 16; i += 256) {
        int r = i >> 4, ch = i & 15;
        CP16(sb + G1_BLO + r * G1_ASTR + ch * 16, wl + (nColBase + r) * 64 + ch * 4);
    }
    CPCOMMIT();

    float c[10][4];
#pragma unroll
    for (int nt = 0; nt < 10; nt++)
#pragma unroll
        for (int q = 0; q < 4; q++) c[nt][q] = 0.f;

    uint32_t aoff = (uint32_t)((wid * 16 + (lane & 7) + ((lane >> 3) & 1) * 8) * G1_ASTR
                               + ((lane >> 4) & 1) * 16);
    uint32_t boff = (uint32_t)((lane & 7) * G1_ASTR + ((lane >> 4) & 1) * 8 * G1_ASTR
                               + ((lane >> 3) & 1) * 16);
    CPWAIT1();
    __syncthreads();
    mma_block<8, 5, G1_ASTR>(sb + G1_AHI + aoff, sb + G1_BHI + boff, c);
    CPWAIT0();
    __syncthreads();
    mma_block<8, 5, G1_ASTR>(sb + G1_AHI + aoff, sb + G1_BLO + boff, c);
    mma_block<8, 5, G1_ASTR>(sb + G1_ALO + aoff, sb + G1_BHI + boff, c);

    int tq = lane >> 2, tp = lane & 3;
    int r0 = row0 + wid * 16 + tq, r1 = r0 + 8;
#pragma unroll
    for (int nt = 0; nt < 10; nt++) {
        if (nt >= nthis) break;
        int col = nColBase + nt * 8 + tp * 2;
        if (r0 < NN) *(float2*)(g_xp + (size_t)r0 * HF + col) = make_float2(c[nt][0], c[nt][1]);
        if (r1 < NN) *(float2*)(g_xp + (size_t)r1 * HF + col) = make_float2(c[nt][2], c[nt][3]);
    }
}

// ================= attention coefficients (permuted xp) =================
__global__ void attn_k(const float* __restrict__ a_s, const float* __restrict__ a_d) {
    __shared__ float ss[HF], sd[HF];
    int t = threadIdx.x;
    if (t < HF) { ss[t] = a_s[ORIG(t)]; sd[t] = a_d[ORIG(t)]; }
    __syncthreads();
    int idx = blockIdx.x * blockDim.x + t;
    if (idx >= NN * HEADS) return;
    int n = idx / HEADS, h = idx % HEADS;
    const float* xr = g_xp + (size_t)n * HF;
    float vs = 0.f, vd = 0.f;
#pragma unroll
    for (int o = 0; o < NOUT; o++) {
        int f = o * 8 + h;
        float x = xr[f];
        vs += x * ss[f];
        vd += x * sd[f];
    }
    g_als[idx] = vs;
    g_ald[idx] = vd;
}

// ==== per-edge softmax weights: pass1 stash logits, pass2 linear rescale ===
__global__ void alpha_k() {
    int gw = (blockIdx.x * blockDim.x + threadIdx.x) >> 5;
    int lane = threadIdx.x & 31;
    if (gw >= NN) return;
    int d = gw;
    int beg = g_off[d], end = g_off[d + 1];

    int eo = lane >> 3, h8 = lane & 7;
    float aldv8 = g_ald[d * HEADS + h8];
    float m = -1e30f, s = 0.f;

    int e0 = beg + eo;
    int sp = (e0 < end) ? g_ssrc[e0] : 0;
    float av = (e0 < end) ? g_als[sp * HEADS + h8] : 0.f;
    for (int e = e0; e < end; e += 4) {
        int en = e + 4;
        int spn = (en < end) ? g_ssrc[en] : 0;
        float avn = (en < end) ? g_als[spn * HEADS + h8] : 0.f;
        float ev = av + aldv8;
        ev = ev > 0.f ? ev : SLOPE * ev;
        g_alpha[(size_t)e * HEADS + h8] = ev;  // stash logit
        float mn = fmaxf(m, ev);
        s = s * __expf(m - mn) + __expf(ev - mn);
        m = mn;
        av = avn;
    }
#pragma unroll
    for (int off = 8; off <= 16; off <<= 1) {
        float mo = __shfl_xor_sync(0xffffffffu, m, off);
        float so = __shfl_xor_sync(0xffffffffu, s, off);
        float mn = fmaxf(m, mo);
        s = s * __expf(m - mn) + so * __expf(mo - mn);
        m = mn;
    }
    float siv = 1.f / (s + SEPS);

    // pass 2: linear read-modify-write (no gather)
    for (int e = e0; e < end; e += 4) {
        float ev = g_alpha[(size_t)e * HEADS + h8];
        g_alpha[(size_t)e * HEADS + h8] = __expf(ev - m) * siv;
    }
}

// ==== aggregation: 4-edge batched gather + bias + layernorm (warp/dst) ====
__global__ void agg_k(const float* __restrict__ gb, const float* __restrict__ lg,
                      const float* __restrict__ lb) {
    int gw = (blockIdx.x * blockDim.x + threadIdx.x) >> 5;
    int lane = threadIdx.x & 31;
    if (gw >= NN) return;
    int d = gw;
    int beg = g_off[d], end = g_off[d + 1];
    int hl = lane & 7;

    float acc[5] = {0.f, 0.f, 0.f, 0.f, 0.f};
    int s[4];
    float al[4];
#pragma unroll
    for (int k = 0; k < 4; k++) {
        int ee = beg + k;
        bool v = ee < end;
        s[k] = v ? g_ssrc[ee] : 0;
        al[k] = v ? g_alpha[(size_t)ee * HEADS + hl] : 0.f;
    }
    for (int e = beg; e < end; e += 4) {
        // prefetch next batch of (src, alpha)
        int s2[4];
        float al2[4];
#pragma unroll
        for (int k = 0; k < 4; k++) {
            int ee = e + 4 + k;
            bool v = ee < end;
            s2[k] = v ? g_ssrc[ee] : 0;
            al2[k] = v ? g_alpha[(size_t)ee * HEADS + hl] : 0.f;
        }
        // 20 independent feature loads (4 rows x 5)
        float xv[4][5];
#pragma unroll
        for (int k = 0; k < 4; k++) {
            const float* xr = g_xp + (size_t)s[k] * HF;
#pragma unroll
            for (int j = 0; j < 5; j++) {
                int f = lane + 32 * j;
                xv[k][j] = (f < HF) ? xr[f] : 0.f;
            }
        }
#pragma unroll
        for (int k = 0; k < 4; k++)
#pragma unroll
            for (int j = 0; j < 5; j++) acc[j] += al[k] * xv[k][j];
#pragma unroll
        for (int k = 0; k < 4; k++) { s[k] = s2[k]; al[k] = al2[k]; }
    }

    // bias + layernorm (params indexed via ORIG)
    float out[5];
    float lsum = 0.f;
#pragma unroll
    for (int j = 0; j < 5; j++) {
        int f = lane + 32 * j;
        if (f < HF) {
            out[j] = acc[j] + gb[ORIG(f)];
            lsum += out[j];
        } else out[j] = 0.f;
    }
#pragma unroll
    for (int o = 16; o > 0; o >>= 1) lsum += __shfl_xor_sync(0xffffffffu, lsum, o);
    float mu = lsum / (float)HF;
    float lvar = 0.f;
#pragma unroll
    for (int j = 0; j < 5; j++) {
        int f = lane + 32 * j;
        if (f < HF) { float dv = out[j] - mu; lvar += dv * dv; }
    }
#pragma unroll
    for (int o = 16; o > 0; o >>= 1) lvar += __shfl_xor_sync(0xffffffffu, lvar, o);
    float inv = rsqrtf(lvar / (float)HF + 1e-5f);

#pragma unroll
    for (int j = 0; j < 5; j++) {
        int f = lane + 32 * j;
        float val = (f < HF) ? (out[j] - mu) * inv * lg[ORIG(f)] + lb[ORIG(f)] : 0.f;
        float v1 = __shfl_down_sync(0xffffffffu, val, 1);
        if ((lane & 1) == 0) {
            int kp = 16 * j + (lane >> 1);
            uint32_t hi, lo;
            split_bf16(val, v1, hi, lo);
            g_uhi[(size_t)d * 80 + kp] = hi;
            g_ulo[(size_t)d * 80 + kp] = lo;
        }
    }
}

// ====== GEMM2: h_new = 2h + u(perm) @ fW(perm rows) + fb; M64 x N64 =======
#define G2_ASTR 336
#define G2_AHI 0
#define G2_ALO 21504
#define G2_BHI 43008
#define G2_BLO 64512
#define G2_SMEM 86016

__global__ __launch_bounds__(256, 2) void gemm2_k(int blk, const float* __restrict__ fb,
                                                  float* dst) {
    extern __shared__ char sm[];
    uint32_t sb = smaddr(sm);
    int t = threadIdx.x, lane = t & 31, wid = t >> 5;
    int row0 = blockIdx.x * 64;
    int ny = blockIdx.y;
    float* o = dst ? dst : g_h;
    const uint32_t* wh = g_w2hi + blk * 128 * 80;
    const uint32_t* wl = g_w2lo + blk * 128 * 80;

    for (int i = t; i < 64 * 20; i += 256) {
        int r = i / 20, ch = i % 20;
        int gr = row0 + r;
        if (gr < NN) CP16(sb + G2_AHI + r * G2_ASTR + ch * 16, g_uhi + (size_t)gr * 80 + ch * 4);
    }
    for (int i = t; i < 64 * 20; i += 256) {
        int r = i / 20, ch = i % 20;
        CP16(sb + G2_BHI + r * G2_ASTR + ch * 16, wh + (ny * 64 + r) * 80 + ch * 4);
    }
    CPCOMMIT();
    for (int i = t; i < 64 * 20; i += 256) {
        int r = i / 20, ch = i % 20;
        int gr = row0 + r;
        if (gr < NN) CP16(sb + G2_ALO + r * G2_ASTR + ch * 16, g_ulo + (size_t)gr * 80 + ch * 4);
    }
    for (int i = t; i < 64 * 20; i += 256) {
        int r = i / 20, ch = i % 20;
        CP16(sb + G2_BLO + r * G2_ASTR + ch * 16, wl + (ny * 64 + r) * 80 + ch * 4);
    }
    CPCOMMIT();

    int wm = wid & 3, wn = wid >> 2;
    float c[4][4];
#pragma unroll
    for (int i = 0; i < 4; i++)
#pragma unroll
        for (int q = 0; q < 4; q++) c[i][q] = 0.f;

    uint32_t aoff = (uint32_t)((wm * 16 + (lane & 7) + ((lane >> 3) & 1) * 8) * G2_ASTR
                               + ((lane >> 4) & 1) * 16);
    uint32_t boff = (uint32_t)((wn * 32 + (lane & 7) + ((lane >> 4) & 1) * 8) * G2_ASTR
                               + ((lane >> 3) & 1) * 16);
    CPWAIT1();
    __syncthreads();
    mma_block<10, 2, G2_ASTR>(sb + G2_AHI + aoff, sb + G2_BHI + boff, c);
    CPWAIT0();
    __syncthreads();
    mma_block<10, 2, G2_ASTR>(sb + G2_AHI + aoff, sb + G2_BLO + boff, c);
    mma_block<10, 2, G2_ASTR>(sb + G2_ALO + aoff, sb + G2_BHI + boff, c);

    int tq = lane >> 2, tp = lane & 3;
    int r0 = row0 + wm * 16 + tq, r1 = r0 + 8;
#pragma unroll
    for (int i = 0; i < 4; i++) {
        int col = ny * 64 + (wn * 4 + i) * 8 + tp * 2;
        float2 fbv = *(const float2*)(fb + col);
        if (r0 < NN) {
            float2 hv = *(const float2*)(g_h + (size_t)r0 * HID + col);
            float ox = 2.f * hv.x + c[i][0] + fbv.x;
            float oy = 2.f * hv.y + c[i][1] + fbv.y;
            *(float2*)(o + (size_t)r0 * HID + col) = make_float2(ox, oy);
            if (!dst) {
                uint32_t hi, lo;
                split_bf16(ox, oy, hi, lo);
                g_hhi[(size_t)r0 * 64 + (col >> 1)] = hi;
                g_hlo[(size_t)r0 * 64 + (col >> 1)] = lo;
            }
        }
        if (r1 < NN) {
            float2 hv = *(const float2*)(g_h + (size_t)r1 * HID + col);
            float ox = 2.f * hv.x + c[i][2] + fbv.x;
            float oy = 2.f * hv.y + c[i][3] + fbv.y;
            *(float2*)(o + (size_t)r1 * HID + col) = make_float2(ox, oy);
            if (!dst) {
                uint32_t hi, lo;
                split_bf16(ox, oy, hi, lo);
                g_hhi[(size_t)r1 * 64 + (col >> 1)] = hi;
                g_hlo[(size_t)r1 * 64 + (col >> 1)] = lo;
            }
        }
    }
}

// ================= launch =================
extern "C" void kernel_launch(void* const* d_in, const int* in_sizes, int n_in,
                              void* d_out, int out_size) {
    const int* z = (const int*)d_in[0];
    const int* ei = (const int*)d_in[2];
    const float* emb = (const float*)d_in[3];
    const float* gat_W = (const float*)d_in[4];
    const float* gat_b = (const float*)d_in[5];
    const float* a_src = (const float*)d_in[6];
    const float* a_dst = (const float*)d_in[7];
    const float* ln_g = (const float*)d_in[8];
    const float* ln_b = (const float*)d_in[9];
    const float* ff_W = (const float*)d_in[10];
    const float* ff_b = (const float*)d_in[11];
    float* outp = (float*)d_out;

    const int* row = ei;
    const int* col = ei + EE;

    cudaFuncSetAttribute(gemm1_k, cudaFuncAttributeMaxDynamicSharedMemorySize, G1_SMEM);
    cudaFuncSetAttribute(gemm2_k, cudaFuncAttributeMaxDynamicSharedMemorySize, G2_SMEM);

    const dim3 G1G((NN + 127) / 128, 2);
    const dim3 G2G((NN + 63) / 64, 2);
    const int WS = 3 * 152 * 64 + 3 * 128 * 80;

    embed_k<<<(NN * 32 + 255) / 256, 256>>>(z, emb);        // idx 0
    wsplit_k<<<(WS + 255) / 256, 256>>>(gat_W, ff_W);       // idx 1
    gemm1_k<<<G1G, 256, G1_SMEM>>>(0);                      // idx 2
    attn_k<<<(NN * HEADS + 255) / 256, 256>>>(a_src, a_dst);// idx 3 <- profiled
    hist_k<<<(EE + 255) / 256, 256>>>(col);
    scan1_k<<<NB, 1024>>>();
    scan23_k<<<(NN + 255) / 256, 256>>>();
    scatter_k<<<(ET + 255) / 256, 256>>>(row, col);
    alpha_k<<<(NN + 7) / 8, 256>>>();
    agg_k<<<(NN + 7) / 8, 256>>>(gat_b, ln_g, ln_b);
    gemm2_k<<<G2G, 256, G2_SMEM>>>(0, ff_b, nullptr);

    for (int b = 1; b < 3; b++) {
        gemm1_k<<<G1G, 256, G1_SMEM>>>(b);
        attn_k<<<(NN * HEADS + 255) / 256, 256>>>(a_src + b * HF, a_dst + b * HF);
        alpha_k<<<(NN + 7) / 8, 256>>>();
        agg_k<<<(NN + 7) / 8, 256>>>(gat_b + b * HF, ln_g + b * HF, ln_b + b * HF);
        gemm2_k<<<G2G, 256, G2_SMEM>>>(b, ff_b + b * HID,
                                       (b == 2) ? outp : nullptr);
    }
}

// round 13
// speedup vs baseline: 1.0979x; 1.0979x over previous
#include <cuda_runtime.h>
#include <cuda_bf16.h>
#include <cstdint>

#define NN 50000
#define EE 800000
#define ET (EE + NN)
#define HID 128
#define HEADS 8
#define NOUT 19
#define HF 152
#define SLOPE 0.2f
#define SEPS 1e-16f
#define NB 49  // ceil(NN/1024)

// permuted feature index f' = o*8+h  ->  original index h*19+o
#define ORIG(f) ((((f) & 7) * 19) + ((f) >> 3))

// ================= scratch =================
__device__ float g_xp[NN * HF];      // PERMUTED feature order (fp32)
__device__ float g_als[NN * HEADS];
__device__ float g_ald[NN * HEADS];
__device__ int g_off[NN + 1];
__device__ int g_cur[NN];
__device__ int g_part[64];
__device__ int g_ssrc[ET];
// pre-split bf16 hi/lo packed pairs (h lives ONLY in this form)
__device__ __align__(16) uint32_t g_hhi[NN * 64];
__device__ __align__(16) uint32_t g_hlo[NN * 64];
__device__ __align__(16) uint32_t g_uhi[NN * 80];
__device__ __align__(16) uint32_t g_ulo[NN * 80];
__device__ __align__(16) uint32_t g_w1hi[3 * 152 * 64];
__device__ __align__(16) uint32_t g_w1lo[3 * 152 * 64];
__device__ __align__(16) uint32_t g_w2hi[3 * 128 * 80];
__device__ __align__(16) uint32_t g_w2lo[3 * 128 * 80];

__device__ __forceinline__ void split_bf16(float a, float b, uint32_t& hi, uint32_t& lo) {
    __nv_bfloat162 h2 = __floats2bfloat162_rn(a, b);
    float la = a - __bfloat162float(h2.x);
    float lb = b - __bfloat162float(h2.y);
    __nv_bfloat162 l2 = __floats2bfloat162_rn(la, lb);
    hi = *(uint32_t*)&h2;
    lo = *(uint32_t*)&l2;
}

__device__ __forceinline__ float2 join_bf16(uint32_t hi, uint32_t lo) {
    __nv_bfloat162 bh = *(__nv_bfloat162*)&hi;
    __nv_bfloat162 bl = *(__nv_bfloat162*)&lo;
    return make_float2(__bfloat162float(bh.x) + __bfloat162float(bl.x),
                       __bfloat162float(bh.y) + __bfloat162float(bl.y));
}

__device__ __forceinline__ void mma_bf16(float* c, uint32_t a0, uint32_t a1, uint32_t a2,
                                         uint32_t a3, uint32_t b0, uint32_t b1) {
    asm volatile(
        "mma.sync.aligned.m16n8k16.row.col.f32.bf16.bf16.f32 "
        "{%0,%1,%2,%3}, {%4,%5,%6,%7}, {%8,%9}, {%0,%1,%2,%3};\n"
        : "+f"(c[0]), "+f"(c[1]), "+f"(c[2]), "+f"(c[3])
        : "r"(a0), "r"(a1), "r"(a2), "r"(a3), "r"(b0), "r"(b1));
}

#define LDMX4(r0, r1, r2, r3, a) \
    asm volatile("ldmatrix.sync.aligned.m8n8.x4.shared.b16 {%0,%1,%2,%3}, [%4];" \
        : "=r"(r0), "=r"(r1), "=r"(r2), "=r"(r3) : "r"(a))

__device__ __forceinline__ uint32_t smaddr(const void* p) {
    return (uint32_t)__cvta_generic_to_shared(p);
}
#define CP16(dst, src) \
    asm volatile("cp.async.cg.shared.global [%0], [%1], 16;" :: "r"(dst), "l"(src))
#define CPCOMMIT() asm volatile("cp.async.commit_group;" ::: "memory")
#define CPWAIT1() asm volatile("cp.async.wait_group 1;" ::: "memory")
#define CPWAIT0() asm volatile("cp.async.wait_group 0;" ::: "memory")

template <int KC, int NTP, int ASTR>
__device__ __forceinline__ void mma_block(uint32_t Ab, uint32_t Bb, float (*c)[4]) {
#pragma unroll
    for (int kc = 0; kc < KC; kc++) {
        uint32_t a0, a1, a2, a3;
        LDMX4(a0, a1, a2, a3, Ab + kc * 32);
#pragma unroll
        for (int ntp = 0; ntp < NTP; ntp++) {
            uint32_t b0, b1, b2, b3;
            LDMX4(b0, b1, b2, b3, Bb + ntp * 16 * ASTR + kc * 32);
            mma_bf16(c[2 * ntp], a0, a1, a2, a3, b0, b1);
            mma_bf16(c[2 * ntp + 1], a0, a1, a2, a3, b2, b3);
        }
    }
}

// ================= setup kernels =================
__global__ void embed_k(const int* __restrict__ z, const float* __restrict__ emb) {
    int idx = blockIdx.x * blockDim.x + threadIdx.x;
    int n = idx >> 5, q = idx & 31;
    if (n >= NN) return;
    int zi = z[n];
    float4 v = ((const float4*)(emb + zi * HID))[q];
    uint32_t h0, l0, h1, l1;
    split_bf16(v.x, v.y, h0, l0);
    split_bf16(v.z, v.w, h1, l1);
    g_hhi[n * 64 + 2 * q] = h0;
    g_hlo[n * 64 + 2 * q] = l0;
    g_hhi[n * 64 + 2 * q + 1] = h1;
    g_hlo[n * 64 + 2 * q + 1] = l1;
    if (q == 0) g_cur[n] = 1;  // self loop
}

__global__ void zero_k() {
    int i = blockIdx.x * blockDim.x + threadIdx.x;
    if (i < NN * HEADS) {
        g_als[i] = 0.f;
        g_ald[i] = 0.f;
    }
}

__global__ void hist_k(const int* __restrict__ col) {
    int e = blockIdx.x * blockDim.x + threadIdx.x;
    if (e < EE) atomicAdd(&g_cur[col[e]], 1);
}

__global__ void wsplit_k(const float* __restrict__ gat_W, const float* __restrict__ ff_W) {
    int idx = blockIdx.x * blockDim.x + threadIdx.x;
    const int N1 = 3 * 152 * 64;
    if (idx < N1) {
        int b = idx / (152 * 64), rem = idx % (152 * 64);
        int n = rem >> 6, kp = rem & 63;
        const float* W = gat_W + b * HID * HF;
        int no = ORIG(n);
        float w0 = W[(2 * kp) * HF + no];
        float w1 = W[(2 * kp + 1) * HF + no];
        uint32_t hi, lo;
        split_bf16(w0, w1, hi, lo);
        g_w1hi[idx] = hi;
        g_w1lo[idx] = lo;
    } else if (idx < N1 + 3 * 128 * 80) {
        int j = idx - N1;
        int b = j / (128 * 80), rem = j % (128 * 80);
        int n = rem / 80, kp = rem % 80;
        uint32_t hi = 0, lo = 0;
        if (kp < 76) {
            const float* W = ff_W + b * HF * HID;
            float w0 = W[ORIG(2 * kp) * HID + n];
            float w1 = W[ORIG(2 * kp + 1) * HID + n];
            split_bf16(w0, w1, hi, lo);
        }
        g_w2hi[j] = hi;
        g_w2lo[j] = lo;
    }
}

__global__ void scan1_k() {
    __shared__ int wsum[32];
    int t = threadIdx.x, lane = t & 31, wid = t >> 5;
    int i = blockIdx.x * 1024 + t;
    int v = (i < NN) ? g_cur[i] : 0;
    int x = v;
#pragma unroll
    for (int d = 1; d < 32; d <<= 1) {
        int y = __shfl_up_sync(0xffffffffu, x, d);
        if (lane >= d) x += y;
    }
    if (lane == 31) wsum[wid] = x;
    __syncthreads();
    if (wid == 0) {
        int y = wsum[lane];
#pragma unroll
        for (int d = 1; d < 32; d <<= 1) {
            int z2 = __shfl_up_sync(0xffffffffu, y, d);
            if (lane >= d) y += z2;
        }
        wsum[lane] = y;
    }
    __syncthreads();
    int excl = (wid > 0 ? wsum[wid - 1] : 0) + x - v;
    if (i < NN) g_off[i] = excl;
    if (t == 1023) g_part[blockIdx.x] = wsum[31];
}

__global__ void scan23_k() {
    __shared__ int sp[64];
    int t = threadIdx.x;
    if (t < 32) {
        int v0 = (t < NB) ? g_part[t] : 0;
        int v1 = (t + 32 < NB) ? g_part[t + 32] : 0;
        int s0 = v0;
#pragma unroll
        for (int d = 1; d < 32; d <<= 1) {
            int y = __shfl_up_sync(0xffffffffu, s0, d);
            if (t >= d) s0 += y;
        }
        int tot0 = __shfl_sync(0xffffffffu, s0, 31);
        int s1 = v1;
#pragma unroll
        for (int d = 1; d < 32; d <<= 1) {
            int y = __shfl_up_sync(0xffffffffu, s1, d);
            if (t >= d) s1 += y;
        }
        sp[t] = s0 - v0;
        sp[t + 32] = tot0 + s1 - v1;
    }
    __syncthreads();
    int i = blockIdx.x * blockDim.x + t;
    if (i < NN) {
        int v = g_off[i] + sp[i >> 10];
        g_off[i] = v;
        g_cur[i] = v;
    }
    if (i == 0) g_off[NN] = ET;
}

__global__ void scatter_k(const int* __restrict__ row, const int* __restrict__ col) {
    int i = blockIdx.x * blockDim.x + threadIdx.x;
    if (i >= ET) return;
    int s, d;
    if (i < EE) { s = row[i]; d = col[i]; }
    else        { s = d = i - EE; }
    int p = atomicAdd(&g_cur[d], 1);
    g_ssrc[p] = s;
}

// ==== GEMM1 + fused attn: xp = h @ W1(perm); als/ald via atomics ==========
#define G1_ASTR 272
#define G1_AHI 0
#define G1_ALO 34816
#define G1_BHI 69632
#define G1_BLO 91392
#define G1_AS 113152                       // float sAS[152]
#define G1_AD (G1_AS + 152 * 4)            // float sAD[152]
#define G1_SMEM (G1_AD + 152 * 4)          // 114368

__global__ __launch_bounds__(256, 2) void gemm1_k(int blk, const float* __restrict__ a_s,
                                                  const float* __restrict__ a_d) {
    extern __shared__ char sm[];
    uint32_t sb = smaddr(sm);
    float* sAS = (float*)(sm + G1_AS);
    float* sAD = (float*)(sm + G1_AD);
    int t = threadIdx.x, lane = t & 31, wid = t >> 5;
    int row0 = blockIdx.x * 128;
    int nh = blockIdx.y;
    int nthis = nh ? 9 : 10;
    int nColBase = nh * 80;
    int bRows = nthis * 8;
    const uint32_t* wh = g_w1hi + blk * 152 * 64;
    const uint32_t* wl = g_w1lo + blk * 152 * 64;

    if (t < HF) {
        sAS[t] = a_s[ORIG(t)];
        sAD[t] = a_d[ORIG(t)];
    }

    for (int i = t; i < 128 * 16; i += 256) {
        int r = i >> 4, ch = i & 15;
        int gr = row0 + r;
        if (gr < NN) CP16(sb + G1_AHI + r * G1_ASTR + ch * 16, g_hhi + (size_t)gr * 64 + ch * 4);
    }
    for (int i = t; i < bRows * 16; i += 256) {
        int r = i >> 4, ch = i & 15;
        CP16(sb + G1_BHI + r * G1_ASTR + ch * 16, wh + (nColBase + r) * 64 + ch * 4);
    }
    CPCOMMIT();
    for (int i = t; i < 128 * 16; i += 256) {
        int r = i >> 4, ch = i & 15;
        int gr = row0 + r;
        if (gr < NN) CP16(sb + G1_ALO + r * G1_ASTR + ch * 16, g_hlo + (size_t)gr * 64 + ch * 4);
    }
    for (int i = t; i < bRows * 16; i += 256) {
        int r = i >> 4, ch = i & 15;
        CP16(sb + G1_BLO + r * G1_ASTR + ch * 16, wl + (nColBase + r) * 64 + ch * 4);
    }
    CPCOMMIT();

    float c[10][4];
#pragma unroll
    for (int nt = 0; nt < 10; nt++)
#pragma unroll
        for (int q = 0; q < 4; q++) c[nt][q] = 0.f;

    uint32_t aoff = (uint32_t)((wid * 16 + (lane & 7) + ((lane >> 3) & 1) * 8) * G1_ASTR
                               + ((lane >> 4) & 1) * 16);
    uint32_t boff = (uint32_t)((lane & 7) * G1_ASTR + ((lane >> 4) & 1) * 8 * G1_ASTR
                               + ((lane >> 3) & 1) * 16);
    CPWAIT1();
    __syncthreads();
    mma_block<8, 5, G1_ASTR>(sb + G1_AHI + aoff, sb + G1_BHI + boff, c);
    CPWAIT0();
    __syncthreads();
    mma_block<8, 5, G1_ASTR>(sb + G1_AHI + aoff, sb + G1_BLO + boff, c);
    mma_block<8, 5, G1_ASTR>(sb + G1_ALO + aoff, sb + G1_BHI + boff, c);

    int tq = lane >> 2, tp = lane & 3;
    int r0 = row0 + wid * 16 + tq, r1 = r0 + 8;
    // attn partials: lane owns heads 2tp (even cols) and 2tp+1 (odd cols)
    float vs0 = 0.f, vs1 = 0.f, vs2 = 0.f, vs3 = 0.f;
    float vd0 = 0.f, vd1 = 0.f, vd2 = 0.f, vd3 = 0.f;
#pragma unroll
    for (int nt = 0; nt < 10; nt++) {
        if (nt >= nthis) break;
        int col = nColBase + nt * 8 + tp * 2;
        float se = sAS[col], so = sAS[col + 1];
        float de = sAD[col], do_ = sAD[col + 1];
        vs0 += c[nt][0] * se; vs1 += c[nt][1] * so;
        vs2 += c[nt][2] * se; vs3 += c[nt][3] * so;
        vd0 += c[nt][0] * de; vd1 += c[nt][1] * do_;
        vd2 += c[nt][2] * de; vd3 += c[nt][3] * do_;
        if (r0 < NN) *(float2*)(g_xp + (size_t)r0 * HF + col) = make_float2(c[nt][0], c[nt][1]);
        if (r1 < NN) *(float2*)(g_xp + (size_t)r1 * HF + col) = make_float2(c[nt][2], c[nt][3]);
    }
    if (r0 < NN) {
        atomicAdd(&g_als[r0 * HEADS + 2 * tp], vs0);
        atomicAdd(&g_als[r0 * HEADS + 2 * tp + 1], vs1);
        atomicAdd(&g_ald[r0 * HEADS + 2 * tp], vd0);
        atomicAdd(&g_ald[r0 * HEADS + 2 * tp + 1], vd1);
    }
    if (r1 < NN) {
        atomicAdd(&g_als[r1 * HEADS + 2 * tp], vs2);
        atomicAdd(&g_als[r1 * HEADS + 2 * tp + 1], vs3);
        atomicAdd(&g_ald[r1 * HEADS + 2 * tp], vd2);
        atomicAdd(&g_ald[r1 * HEADS + 2 * tp + 1], vd3);
    }
}

// ==== aggregation: fused stats + inline-weight gather + layernorm =========
__global__ void agg_k(const float* __restrict__ gb, const float* __restrict__ lg,
                      const float* __restrict__ lb) {
    int gw = (blockIdx.x * blockDim.x + threadIdx.x) >> 5;
    int lane = threadIdx.x & 31;
    if (gw >= NN) return;
    int d = gw;
    int beg = g_off[d], end = g_off[d + 1];
    int eo = lane >> 3, h8 = lane & 7;

    float aldv8 = g_ald[d * HEADS + h8];

    // phase 1: per-head max & sum (4 edges x 8 heads; als is L2-resident)
    float m = -1e30f, s = 0.f;
    for (int e = beg + eo; e < end; e += 4) {
        float ev = g_als[g_ssrc[e] * HEADS + h8] + aldv8;
        ev = ev > 0.f ? ev : SLOPE * ev;
        float mn = fmaxf(m, ev);
        s = s * __expf(m - mn) + __expf(ev - mn);
        m = mn;
    }
#pragma unroll
    for (int off = 8; off <= 16; off <<= 1) {
        float mo = __shfl_xor_sync(0xffffffffu, m, off);
        float so = __shfl_xor_sync(0xffffffffu, s, off);
        float mn = fmaxf(m, mo);
        s = s * __expf(m - mn) + so * __expf(mo - mn);
        m = mn;
    }
    float siv = 1.f / (s + SEPS);
    // every lane now holds (m, siv) for head lane&7

    // phase 2: gather; lane computes weight for (edge eo, head h8) per batch
    float acc[5] = {0.f, 0.f, 0.f, 0.f, 0.f};
    for (int e = beg; e < end; e += 4) {
        int ee = e + eo;
        bool v = ee < end;
        int sv = v ? g_ssrc[ee] : 0;
        float alsv = v ? g_als[sv * HEADS + h8] : 0.f;
        float ev = alsv + aldv8;
        ev = ev > 0.f ? ev : SLOPE * ev;
        float a = v ? __expf(ev - m) * siv : 0.f;
#pragma unroll
        for (int k = 0; k < 4; k++) {
            float ak = __shfl_sync(0xffffffffu, a, k * 8 + h8);
            int sk = __shfl_sync(0xffffffffu, sv, k * 8);
            const float* xr = g_xp + (size_t)sk * HF;
#pragma unroll
            for (int j = 0; j < 5; j++) {
                int f = lane + 32 * j;
                float xv = (f < HF) ? xr[f] : 0.f;
                acc[j] += ak * xv;
            }
        }
    }

    // bias + layernorm (params indexed via ORIG)
    float out[5];
    float lsum = 0.f;
#pragma unroll
    for (int j = 0; j < 5; j++) {
        int f = lane + 32 * j;
        if (f < HF) {
            out[j] = acc[j] + gb[ORIG(f)];
            lsum += out[j];
        } else out[j] = 0.f;
    }
#pragma unroll
    for (int o = 16; o > 0; o >>= 1) lsum += __shfl_xor_sync(0xffffffffu, lsum, o);
    float mu = lsum / (float)HF;
    float lvar = 0.f;
#pragma unroll
    for (int j = 0; j < 5; j++) {
        int f = lane + 32 * j;
        if (f < HF) { float dv = out[j] - mu; lvar += dv * dv; }
    }
#pragma unroll
    for (int o = 16; o > 0; o >>= 1) lvar += __shfl_xor_sync(0xffffffffu, lvar, o);
    float inv = rsqrtf(lvar / (float)HF + 1e-5f);

#pragma unroll
    for (int j = 0; j < 5; j++) {
        int f = lane + 32 * j;
        float val = (f < HF) ? (out[j] - mu) * inv * lg[ORIG(f)] + lb[ORIG(f)] : 0.f;
        float v1 = __shfl_down_sync(0xffffffffu, val, 1);
        if ((lane & 1) == 0) {
            int kp = 16 * j + (lane >> 1);
            uint32_t hi, lo;
            split_bf16(val, v1, hi, lo);
            g_uhi[(size_t)d * 80 + kp] = hi;
            g_ulo[(size_t)d * 80 + kp] = lo;
        }
    }
}

// ====== GEMM2: h_new = 2h + u(perm) @ fW(perm rows) + fb; M64 x N64 =======
#define G2_ASTR 336
#define G2_AHI 0
#define G2_ALO 21504
#define G2_BHI 43008
#define G2_BLO 64512
#define G2_SMEM 86016

__global__ __launch_bounds__(256, 2) void gemm2_k(int blk, const float* __restrict__ fb,
                                                  float* dst) {
    extern __shared__ char sm[];
    uint32_t sb = smaddr(sm);
    int t = threadIdx.x, lane = t & 31, wid = t >> 5;
    int row0 = blockIdx.x * 64;
    int ny = blockIdx.y;
    const uint32_t* wh = g_w2hi + blk * 128 * 80;
    const uint32_t* wl = g_w2lo + blk * 128 * 80;

    for (int i = t; i < 64 * 20; i += 256) {
        int r = i / 20, ch = i % 20;
        int gr = row0 + r;
        if (gr < NN) CP16(sb + G2_AHI + r * G2_ASTR + ch * 16, g_uhi + (size_t)gr * 80 + ch * 4);
    }
    for (int i = t; i < 64 * 20; i += 256) {
        int r = i / 20, ch = i % 20;
        CP16(sb + G2_BHI + r * G2_ASTR + ch * 16, wh + (ny * 64 + r) * 80 + ch * 4);
    }
    CPCOMMIT();
    for (int i = t; i < 64 * 20; i += 256) {
        int r = i / 20, ch = i % 20;
        int gr = row0 + r;
        if (gr < NN) CP16(sb + G2_ALO + r * G2_ASTR + ch * 16, g_ulo + (size_t)gr * 80 + ch * 4);
    }
    for (int i = t; i < 64 * 20; i += 256) {
        int r = i / 20, ch = i % 20;
        CP16(sb + G2_BLO + r * G2_ASTR + ch * 16, wl + (ny * 64 + r) * 80 + ch * 4);
    }
    CPCOMMIT();

    int wm = wid & 3, wn = wid >> 2;
    float c[4][4];
#pragma unroll
    for (int i = 0; i < 4; i++)
#pragma unroll
        for (int q = 0; q < 4; q++) c[i][q] = 0.f;

    uint32_t aoff = (uint32_t)((wm * 16 + (lane & 7) + ((lane >> 3) & 1) * 8) * G2_ASTR
                               + ((lane >> 4) & 1) * 16);
    uint32_t boff = (uint32_t)((wn * 32 + (lane & 7) + ((lane >> 4) & 1) * 8) * G2_ASTR
                               + ((lane >> 3) & 1) * 16);
    CPWAIT1();
    __syncthreads();
    mma_block<10, 2, G2_ASTR>(sb + G2_AHI + aoff, sb + G2_BHI + boff, c);
    CPWAIT0();
    __syncthreads();
    mma_block<10, 2, G2_ASTR>(sb + G2_AHI + aoff, sb + G2_BLO + boff, c);
    mma_block<10, 2, G2_ASTR>(sb + G2_ALO + aoff, sb + G2_BHI + boff, c);

    int tq = lane >> 2, tp = lane & 3;
    int r0 = row0 + wm * 16 + tq, r1 = r0 + 8;
#pragma unroll
    for (int i = 0; i < 4; i++) {
        int col = ny * 64 + (wn * 4 + i) * 8 + tp * 2;
        float2 fbv = *(const float2*)(fb + col);
        if (r0 < NN) {
            size_t pidx = (size_t)r0 * 64 + (col >> 1);
            float2 hv = join_bf16(g_hhi[pidx], g_hlo[pidx]);
            float ox = 2.f * hv.x + c[i][0] + fbv.x;
            float oy = 2.f * hv.y + c[i][1] + fbv.y;
            if (dst) {
                *(float2*)(dst + (size_t)r0 * HID + col) = make_float2(ox, oy);
            } else {
                uint32_t hi, lo;
                split_bf16(ox, oy, hi, lo);
                g_hhi[pidx] = hi;
                g_hlo[pidx] = lo;
            }
        }
        if (r1 < NN) {
            size_t pidx = (size_t)r1 * 64 + (col >> 1);
            float2 hv = join_bf16(g_hhi[pidx], g_hlo[pidx]);
            float ox = 2.f * hv.x + c[i][2] + fbv.x;
            float oy = 2.f * hv.y + c[i][3] + fbv.y;
            if (dst) {
                *(float2*)(dst + (size_t)r1 * HID + col) = make_float2(ox, oy);
            } else {
                uint32_t hi, lo;
                split_bf16(ox, oy, hi, lo);
                g_hhi[pidx] = hi;
                g_hlo[pidx] = lo;
            }
        }
    }
}

// ================= launch =================
extern "C" void kernel_launch(void* const* d_in, const int* in_sizes, int n_in,
                              void* d_out, int out_size) {
    const int* z = (const int*)d_in[0];
    const int* ei = (const int*)d_in[2];
    const float* emb = (const float*)d_in[3];
    const float* gat_W = (const float*)d_in[4];
    const float* gat_b = (const float*)d_in[5];
    const float* a_src = (const float*)d_in[6];
    const float* a_dst = (const float*)d_in[7];
    const float* ln_g = (const float*)d_in[8];
    const float* ln_b = (const float*)d_in[9];
    const float* ff_W = (const float*)d_in[10];
    const float* ff_b = (const float*)d_in[11];
    float* outp = (float*)d_out;

    const int* row = ei;
    const int* col = ei + EE;

    cudaFuncSetAttribute(gemm1_k, cudaFuncAttributeMaxDynamicSharedMemorySize, G1_SMEM);
    cudaFuncSetAttribute(gemm2_k, cudaFuncAttributeMaxDynamicSharedMemorySize, G2_SMEM);

    const dim3 G1G((NN + 127) / 128, 2);
    const dim3 G2G((NN + 63) / 64, 2);
    const int WS = 3 * 152 * 64 + 3 * 128 * 80;

    embed_k<<<(NN * 32 + 255) / 256, 256>>>(z, emb);            // idx 0
    wsplit_k<<<(WS + 255) / 256, 256>>>(gat_W, ff_W);           // idx 1
    zero_k<<<(NN * HEADS + 255) / 256, 256>>>();                // idx 2
    gemm1_k<<<G1G, 256, G1_SMEM>>>(0, a_src, a_dst);            // idx 3 <- profiled
    hist_k<<<(EE + 255) / 256, 256>>>(col);
    scan1_k<<<NB, 1024>>>();
    scan23_k<<<(NN + 255) / 256, 256>>>();
    scatter_k<<<(ET + 255) / 256, 256>>>(row, col);
    agg_k<<<(NN + 7) / 8, 256>>>(gat_b, ln_g, ln_b);
    gemm2_k<<<G2G, 256, G2_SMEM>>>(0, ff_b, nullptr);

    for (int b = 1; b < 3; b++) {
        zero_k<<<(NN * HEADS + 255) / 256, 256>>>();
        gemm1_k<<<G1G, 256, G1_SMEM>>>(b, a_src + b * HF, a_dst + b * HF);
        agg_k<<<(NN + 7) / 8, 256>>>(gat_b + b * HF, ln_g + b * HF, ln_b + b * HF);
        gemm2_k<<<G2G, 256, G2_SMEM>>>(b, ff_b + b * HID,
                                       (b == 2) ? outp : nullptr);
    }
}

// round 14
// speedup vs baseline: 1.1316x; 1.0307x over previous
#include <cuda_runtime.h>
#include <cuda_bf16.h>
#include <cstdint>

#define NN 50000
#define EE 800000
#define ET (EE + NN)
#define HID 128
#define HEADS 8
#define NOUT 19
#define HF 152
#define SLOPE 0.2f
#define SEPS 1e-16f
#define NB 49  // ceil(NN/1024)

// permuted feature index f' = o*8+h  ->  original index h*19+o
#define ORIG(f) ((((f) & 7) * 19) + ((f) >> 3))

// ================= scratch =================
__device__ float g_xp[NN * HF];      // PERMUTED feature order (fp32)
__device__ float g_als0[NN * HEADS]; // attn partials, nh=0 CTA
__device__ float g_als1[NN * HEADS]; // attn partials, nh=1 CTA
__device__ float g_ald0[NN * HEADS];
__device__ float g_ald1[NN * HEADS];
__device__ int g_off[NN + 1];
__device__ int g_cur[NN];
__device__ int g_part[64];
__device__ int g_ssrc[ET];
// pre-split bf16 hi/lo packed pairs (h lives ONLY in this form)
__device__ __align__(16) uint32_t g_hhi[NN * 64];
__device__ __align__(16) uint32_t g_hlo[NN * 64];
__device__ __align__(16) uint32_t g_uhi[NN * 80];
__device__ __align__(16) uint32_t g_ulo[NN * 80];
__device__ __align__(16) uint32_t g_w1hi[3 * 152 * 64];
__device__ __align__(16) uint32_t g_w1lo[3 * 152 * 64];
__device__ __align__(16) uint32_t g_w2hi[3 * 128 * 80];
__device__ __align__(16) uint32_t g_w2lo[3 * 128 * 80];

__device__ __forceinline__ void split_bf16(float a, float b, uint32_t& hi, uint32_t& lo) {
    __nv_bfloat162 h2 = __floats2bfloat162_rn(a, b);
    float la = a - __bfloat162float(h2.x);
    float lb = b - __bfloat162float(h2.y);
    __nv_bfloat162 l2 = __floats2bfloat162_rn(la, lb);
    hi = *(uint32_t*)&h2;
    lo = *(uint32_t*)&l2;
}

__device__ __forceinline__ float2 join_bf16(uint32_t hi, uint32_t lo) {
    __nv_bfloat162 bh = *(__nv_bfloat162*)&hi;
    __nv_bfloat162 bl = *(__nv_bfloat162*)&lo;
    return make_float2(__bfloat162float(bh.x) + __bfloat162float(bl.x),
                       __bfloat162float(bh.y) + __bfloat162float(bl.y));
}

__device__ __forceinline__ void mma_bf16(float* c, uint32_t a0, uint32_t a1, uint32_t a2,
                                         uint32_t a3, uint32_t b0, uint32_t b1) {
    asm volatile(
        "mma.sync.aligned.m16n8k16.row.col.f32.bf16.bf16.f32 "
        "{%0,%1,%2,%3}, {%4,%5,%6,%7}, {%8,%9}, {%0,%1,%2,%3};\n"
        : "+f"(c[0]), "+f"(c[1]), "+f"(c[2]), "+f"(c[3])
        : "r"(a0), "r"(a1), "r"(a2), "r"(a3), "r"(b0), "r"(b1));
}

#define LDMX4(r0, r1, r2, r3, a) \
    asm volatile("ldmatrix.sync.aligned.m8n8.x4.shared.b16 {%0,%1,%2,%3}, [%4];" \
        : "=r"(r0), "=r"(r1), "=r"(r2), "=r"(r3) : "r"(a))

__device__ __forceinline__ uint32_t smaddr(const void* p) {
    return (uint32_t)__cvta_generic_to_shared(p);
}
#define CP16(dst, src) \
    asm volatile("cp.async.cg.shared.global [%0], [%1], 16;" :: "r"(dst), "l"(src))
#define CPCOMMIT() asm volatile("cp.async.commit_group;" ::: "memory")
#define CPWAIT0() asm volatile("cp.async.wait_group 0;" ::: "memory")

// interleaved 3-product mainloop with shared-operand register caching:
// per kc: 2 A-ldsm (hi,lo) + 2*NTP B-ldsm (hi,lo) -> 6*NTP mma
template <int KC, int NTP, int ASTR>
__device__ __forceinline__ void mma_fused(uint32_t AH, uint32_t AL, uint32_t BH,
                                          uint32_t BL, float (*c)[4]) {
#pragma unroll
    for (int kc = 0; kc < KC; kc++) {
        uint32_t ah0, ah1, ah2, ah3, al0, al1, al2, al3;
        LDMX4(ah0, ah1, ah2, ah3, AH + kc * 32);
        LDMX4(al0, al1, al2, al3, AL + kc * 32);
#pragma unroll
        for (int ntp = 0; ntp < NTP; ntp++) {
            uint32_t bh0, bh1, bh2, bh3, bl0, bl1, bl2, bl3;
            LDMX4(bh0, bh1, bh2, bh3, BH + ntp * 16 * ASTR + kc * 32);
            LDMX4(bl0, bl1, bl2, bl3, BL + ntp * 16 * ASTR + kc * 32);
            mma_bf16(c[2 * ntp], ah0, ah1, ah2, ah3, bh0, bh1);
            mma_bf16(c[2 * ntp + 1], ah0, ah1, ah2, ah3, bh2, bh3);
            mma_bf16(c[2 * ntp], ah0, ah1, ah2, ah3, bl0, bl1);
            mma_bf16(c[2 * ntp + 1], ah0, ah1, ah2, ah3, bl2, bl3);
            mma_bf16(c[2 * ntp], al0, al1, al2, al3, bh0, bh1);
            mma_bf16(c[2 * ntp + 1], al0, al1, al2, al3, bh2, bh3);
        }
    }
}

// ================= setup kernels =================
__global__ void embed_k(const int* __restrict__ z, const float* __restrict__ emb) {
    int idx = blockIdx.x * blockDim.x + threadIdx.x;
    int n = idx >> 5, q = idx & 31;
    if (n >= NN) return;
    int zi = z[n];
    float4 v = ((const float4*)(emb + zi * HID))[q];
    uint32_t h0, l0, h1, l1;
    split_bf16(v.x, v.y, h0, l0);
    split_bf16(v.z, v.w, h1, l1);
    g_hhi[n * 64 + 2 * q] = h0;
    g_hlo[n * 64 + 2 * q] = l0;
    g_hhi[n * 64 + 2 * q + 1] = h1;
    g_hlo[n * 64 + 2 * q + 1] = l1;
    if (q == 0) g_cur[n] = 1;  // self loop
}

__global__ void hist_k(const int* __restrict__ col) {
    int e = blockIdx.x * blockDim.x + threadIdx.x;
    if (e < EE) atomicAdd(&g_cur[col[e]], 1);
}

__global__ void wsplit_k(const float* __restrict__ gat_W, const float* __restrict__ ff_W) {
    int idx = blockIdx.x * blockDim.x + threadIdx.x;
    const int N1 = 3 * 152 * 64;
    if (idx < N1) {
        int b = idx / (152 * 64), rem = idx % (152 * 64);
        int n = rem >> 6, kp = rem & 63;
        const float* W = gat_W + b * HID * HF;
        int no = ORIG(n);
        float w0 = W[(2 * kp) * HF + no];
        float w1 = W[(2 * kp + 1) * HF + no];
        uint32_t hi, lo;
        split_bf16(w0, w1, hi, lo);
        g_w1hi[idx] = hi;
        g_w1lo[idx] = lo;
    } else if (idx < N1 + 3 * 128 * 80) {
        int j = idx - N1;
        int b = j / (128 * 80), rem = j % (128 * 80);
        int n = rem / 80, kp = rem % 80;
        uint32_t hi = 0, lo = 0;
        if (kp < 76) {
            const float* W = ff_W + b * HF * HID;
            float w0 = W[ORIG(2 * kp) * HID + n];
            float w1 = W[ORIG(2 * kp + 1) * HID + n];
            split_bf16(w0, w1, hi, lo);
        }
        g_w2hi[j] = hi;
        g_w2lo[j] = lo;
    }
}

__global__ void scan1_k() {
    __shared__ int wsum[32];
    int t = threadIdx.x, lane = t & 31, wid = t >> 5;
    int i = blockIdx.x * 1024 + t;
    int v = (i < NN) ? g_cur[i] : 0;
    int x = v;
#pragma unroll
    for (int d = 1; d < 32; d <<= 1) {
        int y = __shfl_up_sync(0xffffffffu, x, d);
        if (lane >= d) x += y;
    }
    if (lane == 31) wsum[wid] = x;
    __syncthreads();
    if (wid == 0) {
        int y = wsum[lane];
#pragma unroll
        for (int d = 1; d < 32; d <<= 1) {
            int z2 = __shfl_up_sync(0xffffffffu, y, d);
            if (lane >= d) y += z2;
        }
        wsum[lane] = y;
    }
    __syncthreads();
    int excl = (wid > 0 ? wsum[wid - 1] : 0) + x - v;
    if (i < NN) g_off[i] = excl;
    if (t == 1023) g_part[blockIdx.x] = wsum[31];
}

__global__ void scan23_k() {
    __shared__ int sp[64];
    int t = threadIdx.x;
    if (t < 32) {
        int v0 = (t < NB) ? g_part[t] : 0;
        int v1 = (t + 32 < NB) ? g_part[t + 32] : 0;
        int s0 = v0;
#pragma unroll
        for (int d = 1; d < 32; d <<= 1) {
            int y = __shfl_up_sync(0xffffffffu, s0, d);
            if (t >= d) s0 += y;
        }
        int tot0 = __shfl_sync(0xffffffffu, s0, 31);
        int s1 = v1;
#pragma unroll
        for (int d = 1; d < 32; d <<= 1) {
            int y = __shfl_up_sync(0xffffffffu, s1, d);
            if (t >= d) s1 += y;
        }
        sp[t] = s0 - v0;
        sp[t + 32] = tot0 + s1 - v1;
    }
    __syncthreads();
    int i = blockIdx.x * blockDim.x + t;
    if (i < NN) {
        int v = g_off[i] + sp[i >> 10];
        g_off[i] = v;
        g_cur[i] = v;
    }
    if (i == 0) g_off[NN] = ET;
}

__global__ void scatter_k(const int* __restrict__ row, const int* __restrict__ col) {
    int i = blockIdx.x * blockDim.x + threadIdx.x;
    if (i >= ET) return;
    int s, d;
    if (i < EE) { s = row[i]; d = col[i]; }
    else        { s = d = i - EE; }
    int p = atomicAdd(&g_cur[d], 1);
    g_ssrc[p] = s;
}

// ==== GEMM1 + fused attn: xp = h @ W1(perm); per-nh attn partials ==========
#define G1_ASTR 272
#define G1_AHI 0
#define G1_ALO 34816
#define G1_BHI 69632
#define G1_BLO 91392
#define G1_AS 113152                       // float sAS[152]
#define G1_AD (G1_AS + 152 * 4)            // float sAD[152]
#define G1_SMEM (G1_AD + 152 * 4)          // 114368

__global__ __launch_bounds__(256, 2) void gemm1_k(int blk, const float* __restrict__ a_s,
                                                  const float* __restrict__ a_d) {
    extern __shared__ char sm[];
    uint32_t sb = smaddr(sm);
    float* sAS = (float*)(sm + G1_AS);
    float* sAD = (float*)(sm + G1_AD);
    int t = threadIdx.x, lane = t & 31, wid = t >> 5;
    int row0 = blockIdx.x * 128;
    int nh = blockIdx.y;
    int nthis = nh ? 9 : 10;
    int nColBase = nh * 80;
    int bRows = nthis * 8;
    const uint32_t* wh = g_w1hi + blk * 152 * 64;
    const uint32_t* wl = g_w1lo + blk * 152 * 64;
    float* alsP = nh ? g_als1 : g_als0;
    float* aldP = nh ? g_ald1 : g_ald0;

    if (t < HF) {
        sAS[t] = a_s[ORIG(t)];
        sAD[t] = a_d[ORIG(t)];
    }

    for (int i = t; i < 128 * 16; i += 256) {
        int r = i >> 4, ch = i & 15;
        int gr = row0 + r;
        if (gr < NN) {
            uint32_t d0 = sb + G1_AHI + r * G1_ASTR + ch * 16;
            CP16(d0, g_hhi + (size_t)gr * 64 + ch * 4);
            CP16(d0 + (G1_ALO - G1_AHI), g_hlo + (size_t)gr * 64 + ch * 4);
        }
    }
    for (int i = t; i < bRows * 16; i += 256) {
        int r = i >> 4, ch = i & 15;
        uint32_t d0 = sb + G1_BHI + r * G1_ASTR + ch * 16;
        CP16(d0, wh + (nColBase + r) * 64 + ch * 4);
        CP16(d0 + (G1_BLO - G1_BHI), wl + (nColBase + r) * 64 + ch * 4);
    }
    CPCOMMIT();

    float c[10][4];
#pragma unroll
    for (int nt = 0; nt < 10; nt++)
#pragma unroll
        for (int q = 0; q < 4; q++) c[nt][q] = 0.f;

    uint32_t aoff = (uint32_t)((wid * 16 + (lane & 7) + ((lane >> 3) & 1) * 8) * G1_ASTR
                               + ((lane >> 4) & 1) * 16);
    uint32_t boff = (uint32_t)((lane & 7) * G1_ASTR + ((lane >> 4) & 1) * 8 * G1_ASTR
                               + ((lane >> 3) & 1) * 16);
    CPWAIT0();
    __syncthreads();
    mma_fused<8, 5, G1_ASTR>(sb + G1_AHI + aoff, sb + G1_ALO + aoff,
                             sb + G1_BHI + boff, sb + G1_BLO + boff, c);

    int tq = lane >> 2, tp = lane & 3;
    int r0 = row0 + wid * 16 + tq, r1 = r0 + 8;
    // attn partials: lane owns heads 2tp (even cols) and 2tp+1 (odd cols)
    float vs0 = 0.f, vs1 = 0.f, vs2 = 0.f, vs3 = 0.f;
    float vd0 = 0.f, vd1 = 0.f, vd2 = 0.f, vd3 = 0.f;
#pragma unroll
    for (int nt = 0; nt < 10; nt++) {
        if (nt >= nthis) break;
        int col = nColBase + nt * 8 + tp * 2;
        float se = sAS[col], so = sAS[col + 1];
        float de = sAD[col], do_ = sAD[col + 1];
        vs0 += c[nt][0] * se; vs1 += c[nt][1] * so;
        vs2 += c[nt][2] * se; vs3 += c[nt][3] * so;
        vd0 += c[nt][0] * de; vd1 += c[nt][1] * do_;
        vd2 += c[nt][2] * de; vd3 += c[nt][3] * do_;
        if (r0 < NN) *(float2*)(g_xp + (size_t)r0 * HF + col) = make_float2(c[nt][0], c[nt][1]);
        if (r1 < NN) *(float2*)(g_xp + (size_t)r1 * HF + col) = make_float2(c[nt][2], c[nt][3]);
    }
    if (r0 < NN) {
        alsP[r0 * HEADS + 2 * tp] = vs0;
        alsP[r0 * HEADS + 2 * tp + 1] = vs1;
        aldP[r0 * HEADS + 2 * tp] = vd0;
        aldP[r0 * HEADS + 2 * tp + 1] = vd1;
    }
    if (r1 < NN) {
        alsP[r1 * HEADS + 2 * tp] = vs2;
        alsP[r1 * HEADS + 2 * tp + 1] = vs3;
        aldP[r1 * HEADS + 2 * tp] = vd2;
        aldP[r1 * HEADS + 2 * tp + 1] = vd3;
    }
}

// ==== aggregation: fused stats + inline-weight gather + layernorm =========
__global__ void agg_k(const float* __restrict__ gb, const float* __restrict__ lg,
                      const float* __restrict__ lb) {
    int gw = (blockIdx.x * blockDim.x + threadIdx.x) >> 5;
    int lane = threadIdx.x & 31;
    if (gw >= NN) return;
    int d = gw;
    int beg = g_off[d], end = g_off[d + 1];
    int eo = lane >> 3, h8 = lane & 7;

    float aldv8 = g_ald0[d * HEADS + h8] + g_ald1[d * HEADS + h8];

    // phase 1: per-head max & sum (4 edges x 8 heads; als arrays L2-resident)
    float m = -1e30f, s = 0.f;
    for (int e = beg + eo; e < end; e += 4) {
        int sv = g_ssrc[e];
        float ev = g_als0[sv * HEADS + h8] + g_als1[sv * HEADS + h8] + aldv8;
        ev = ev > 0.f ? ev : SLOPE * ev;
        float mn = fmaxf(m, ev);
        s = s * __expf(m - mn) + __expf(ev - mn);
        m = mn;
    }
#pragma unroll
    for (int off = 8; off <= 16; off <<= 1) {
        float mo = __shfl_xor_sync(0xffffffffu, m, off);
        float so = __shfl_xor_sync(0xffffffffu, s, off);
        float mn = fmaxf(m, mo);
        s = s * __expf(m - mn) + so * __expf(mo - mn);
        m = mn;
    }
    float siv = 1.f / (s + SEPS);

    // phase 2: gather; lane computes weight for (edge eo, head h8) per batch
    float acc[5] = {0.f, 0.f, 0.f, 0.f, 0.f};
    for (int e = beg; e < end; e += 4) {
        int ee = e + eo;
        bool v = ee < end;
        int sv = v ? g_ssrc[ee] : 0;
        float alsv = v ? (g_als0[sv * HEADS + h8] + g_als1[sv * HEADS + h8]) : 0.f;
        float ev = alsv + aldv8;
        ev = ev > 0.f ? ev : SLOPE * ev;
        float a = v ? __expf(ev - m) * siv : 0.f;
#pragma unroll
        for (int k = 0; k < 4; k++) {
            float ak = __shfl_sync(0xffffffffu, a, k * 8 + h8);
            int sk = __shfl_sync(0xffffffffu, sv, k * 8);
            const float* xr = g_xp + (size_t)sk * HF;
#pragma unroll
            for (int j = 0; j < 5; j++) {
                int f = lane + 32 * j;
                float xv = (f < HF) ? xr[f] : 0.f;
                acc[j] += ak * xv;
            }
        }
    }

    // bias + layernorm (params indexed via ORIG)
    float out[5];
    float lsum = 0.f;
#pragma unroll
    for (int j = 0; j < 5; j++) {
        int f = lane + 32 * j;
        if (f < HF) {
            out[j] = acc[j] + gb[ORIG(f)];
            lsum += out[j];
        } else out[j] = 0.f;
    }
#pragma unroll
    for (int o = 16; o > 0; o >>= 1) lsum += __shfl_xor_sync(0xffffffffu, lsum, o);
    float mu = lsum / (float)HF;
    float lvar = 0.f;
#pragma unroll
    for (int j = 0; j < 5; j++) {
        int f = lane + 32 * j;
        if (f < HF) { float dv = out[j] - mu; lvar += dv * dv; }
    }
#pragma unroll
    for (int o = 16; o > 0; o >>= 1) lvar += __shfl_xor_sync(0xffffffffu, lvar, o);
    float inv = rsqrtf(lvar / (float)HF + 1e-5f);

#pragma unroll
    for (int j = 0; j < 5; j++) {
        int f = lane + 32 * j;
        float val = (f < HF) ? (out[j] - mu) * inv * lg[ORIG(f)] + lb[ORIG(f)] : 0.f;
        float v1 = __shfl_down_sync(0xffffffffu, val, 1);
        if ((lane & 1) == 0) {
            int kp = 16 * j + (lane >> 1);
            uint32_t hi, lo;
            split_bf16(val, v1, hi, lo);
            g_uhi[(size_t)d * 80 + kp] = hi;
            g_ulo[(size_t)d * 80 + kp] = lo;
        }
    }
}

// ====== GEMM2: h_new = 2h + u(perm) @ fW(perm rows) + fb; M64 x N64 =======
#define G2_ASTR 336
#define G2_AHI 0
#define G2_ALO 21504
#define G2_BHI 43008
#define G2_BLO 64512
#define G2_SMEM 86016

__global__ __launch_bounds__(256, 2) void gemm2_k(int blk, const float* __restrict__ fb,
                                                  float* dst) {
    extern __shared__ char sm[];
    uint32_t sb = smaddr(sm);
    int t = threadIdx.x, lane = t & 31, wid = t >> 5;
    int row0 = blockIdx.x * 64;
    int ny = blockIdx.y;
    const uint32_t* wh = g_w2hi + blk * 128 * 80;
    const uint32_t* wl = g_w2lo + blk * 128 * 80;

    for (int i = t; i < 64 * 20; i += 256) {
        int r = i / 20, ch = i % 20;
        int gr = row0 + r;
        if (gr < NN) {
            uint32_t d0 = sb + G2_AHI + r * G2_ASTR + ch * 16;
            CP16(d0, g_uhi + (size_t)gr * 80 + ch * 4);
            CP16(d0 + (G2_ALO - G2_AHI), g_ulo + (size_t)gr * 80 + ch * 4);
        }
    }
    for (int i = t; i < 64 * 20; i += 256) {
        int r = i / 20, ch = i % 20;
        uint32_t d0 = sb + G2_BHI + r * G2_ASTR + ch * 16;
        CP16(d0, wh + (ny * 64 + r) * 80 + ch * 4);
        CP16(d0 + (G2_BLO - G2_BHI), wl + (ny * 64 + r) * 80 + ch * 4);
    }
    CPCOMMIT();

    int wm = wid & 3, wn = wid >> 2;
    float c[4][4];
#pragma unroll
    for (int i = 0; i < 4; i++)
#pragma unroll
        for (int q = 0; q < 4; q++) c[i][q] = 0.f;

    uint32_t aoff = (uint32_t)((wm * 16 + (lane & 7) + ((lane >> 3) & 1) * 8) * G2_ASTR
                               + ((lane >> 4) & 1) * 16);
    uint32_t boff = (uint32_t)((wn * 32 + (lane & 7) + ((lane >> 4) & 1) * 8) * G2_ASTR
                               + ((lane >> 3) & 1) * 16);
    CPWAIT0();
    __syncthreads();
    mma_fused<10, 2, G2_ASTR>(sb + G2_AHI + aoff, sb + G2_ALO + aoff,
                              sb + G2_BHI + boff, sb + G2_BLO + boff, c);

    int tq = lane >> 2, tp = lane & 3;
    int r0 = row0 + wm * 16 + tq, r1 = r0 + 8;
#pragma unroll
    for (int i = 0; i < 4; i++) {
        int col = ny * 64 + (wn * 4 + i) * 8 + tp * 2;
        float2 fbv = *(const float2*)(fb + col);
        if (r0 < NN) {
            size_t pidx = (size_t)r0 * 64 + (col >> 1);
            float2 hv = join_bf16(g_hhi[pidx], g_hlo[pidx]);
            float ox = 2.f * hv.x + c[i][0] + fbv.x;
            float oy = 2.f * hv.y + c[i][1] + fbv.y;
            if (dst) {
                *(float2*)(dst + (size_t)r0 * HID + col) = make_float2(ox, oy);
            } else {
                uint32_t hi, lo;
                split_bf16(ox, oy, hi, lo);
                g_hhi[pidx] = hi;
                g_hlo[pidx] = lo;
            }
        }
        if (r1 < NN) {
            size_t pidx = (size_t)r1 * 64 + (col >> 1);
            float2 hv = join_bf16(g_hhi[pidx], g_hlo[pidx]);
            float ox = 2.f * hv.x + c[i][2] + fbv.x;
            float oy = 2.f * hv.y + c[i][3] + fbv.y;
            if (dst) {
                *(float2*)(dst + (size_t)r1 * HID + col) = make_float2(ox, oy);
            } else {
                uint32_t hi, lo;
                split_bf16(ox, oy, hi, lo);
                g_hhi[pidx] = hi;
                g_hlo[pidx] = lo;
            }
        }
    }
}

// ================= launch =================
extern "C" void kernel_launch(void* const* d_in, const int* in_sizes, int n_in,
                              void* d_out, int out_size) {
    const int* z = (const int*)d_in[0];
    const int* ei = (const int*)d_in[2];
    const float* emb = (const float*)d_in[3];
    const float* gat_W = (const float*)d_in[4];
    const float* gat_b = (const float*)d_in[5];
    const float* a_src = (const float*)d_in[6];
    const float* a_dst = (const float*)d_in[7];
    const float* ln_g = (const float*)d_in[8];
    const float* ln_b = (const float*)d_in[9];
    const float* ff_W = (const float*)d_in[10];
    const float* ff_b = (const float*)d_in[11];
    float* outp = (float*)d_out;

    const int* row = ei;
    const int* col = ei + EE;

    cudaFuncSetAttribute(gemm1_k, cudaFuncAttributeMaxDynamicSharedMemorySize, G1_SMEM);
    cudaFuncSetAttribute(gemm2_k, cudaFuncAttributeMaxDynamicSharedMemorySize, G2_SMEM);

    const dim3 G1G((NN + 127) / 128, 2);
    const dim3 G2G((NN + 63) / 64, 2);
    const int WS = 3 * 152 * 64 + 3 * 128 * 80;

    embed_k<<<(NN * 32 + 255) / 256, 256>>>(z, emb);            // idx 0
    wsplit_k<<<(WS + 255) / 256, 256>>>(gat_W, ff_W);           // idx 1
    gemm1_k<<<G1G, 256, G1_SMEM>>>(0, a_src, a_dst);            // idx 2
    hist_k<<<(EE + 255) / 256, 256>>>(col);                     // idx 3 <- profiled
    scan1_k<<<NB, 1024>>>();
    scan23_k<<<(NN + 255) / 256, 256>>>();
    scatter_k<<<(ET + 255) / 256, 256>>>(row, col);
    agg_k<<<(NN + 7) / 8, 256>>>(gat_b, ln_g, ln_b);
    gemm2_k<<<G2G, 256, G2_SMEM>>>(0, ff_b, nullptr);

    for (int b = 1; b < 3; b++) {
        gemm1_k<<<G1G, 256, G1_SMEM>>>(b, a_src + b * HF, a_dst + b * HF);
        agg_k<<<(NN + 7) / 8, 256>>>(gat_b + b * HF, ln_g + b * HF, ln_b + b * HF);
        gemm2_k<<<G2G, 256, G2_SMEM>>>(b, ff_b + b * HID,
                                       (b == 2) ? outp : nullptr);
    }
}